// round 1
// baseline (speedup 1.0000x reference)
#include <cuda_runtime.h>

#define BB 32
#define CC 256
#define HW 32
#define EE 8
#define KELEM (CC*CC*9)     // 589824 weight elements per expert / per combined sample
#define BN_EPS 1e-5f

// ---- scratch (no allocations allowed) ----
__device__ float g_r[BB*EE];
__device__ float g_kbuf[(size_t)BB*KELEM];        // combined per-sample kernels [b][oc][ic][9]
__device__ float g_out1[(size_t)BB*CC*HW*HW];     // intermediate activation

// ============================================================================
// Router: GAP -> Linear(C,E) -> sigmoid   (grid=B, block=C)
// ============================================================================
__global__ void router_kernel(const float* __restrict__ x,
                              const float* __restrict__ rw,
                              const float* __restrict__ rb) {
    __shared__ float means[CC];
    int b = blockIdx.x, c = threadIdx.x;
    const float4* xp = (const float4*)(x + ((size_t)b*CC + c)*(HW*HW));
    float s = 0.f;
    #pragma unroll 8
    for (int i = 0; i < HW*HW/4; i++) {
        float4 v = xp[i];
        s += v.x + v.y + v.z + v.w;
    }
    means[c] = s * (1.0f/(HW*HW));
    __syncthreads();
    if (c < EE) {
        float d = rb[c];
        #pragma unroll 8
        for (int k = 0; k < CC; k++) d = fmaf(means[k], rw[c*CC + k], d);
        g_r[b*EE + c] = 1.0f / (1.0f + expf(-d));
    }
}

// ============================================================================
// Combine: g_kbuf[b][j] = sum_e r[b][e] * wbank[e][j]
// Each thread owns one float4 slot j, reads the 8 expert values once,
// emits all 32 batches  (grid = KELEM/4/256 = 576, block = 256)
// ============================================================================
__global__ void combine_kernel(const float* __restrict__ wbank) {
    __shared__ float rs[BB*EE];
    int tid = threadIdx.x;
    if (tid < BB*EE) rs[tid] = g_r[tid];
    __syncthreads();

    int j = blockIdx.x * blockDim.x + tid;           // float4 index
    const float4* w4 = (const float4*)wbank;
    float4 wv[EE];
    #pragma unroll
    for (int e = 0; e < EE; e++) wv[e] = w4[(size_t)e*(KELEM/4) + j];

    float4* out4 = (float4*)g_kbuf;
    #pragma unroll
    for (int b = 0; b < BB; b++) {
        float4 a = make_float4(0.f, 0.f, 0.f, 0.f);
        #pragma unroll
        for (int e = 0; e < EE; e++) {
            float r = rs[b*EE + e];
            a.x = fmaf(r, wv[e].x, a.x);
            a.y = fmaf(r, wv[e].y, a.y);
            a.z = fmaf(r, wv[e].z, a.z);
            a.w = fmaf(r, wv[e].w, a.w);
        }
        out4[(size_t)b*(KELEM/4) + j] = a;
    }
}

// ============================================================================
// Fused conv3x3 (pad=1) + BN + [residual] + ReLU
// grid = (H, B), block = 256. Thread tile: 8 oc x 4 w, one h row per CTA.
// RESID=false: in = x_orig, out = g_out1
// RESID=true : in = g_out1, residual = x_orig, out = param
// ============================================================================
template<bool RESID>
__global__ void conv_kernel(const float* __restrict__ x_orig,
                            const float* __restrict__ gg, const float* __restrict__ gb,
                            const float* __restrict__ gm, const float* __restrict__ gv,
                            float* __restrict__ out_param) {
    __shared__ float wts[CC][37];       // [oc][4 ic * 9 taps + pad]
    __shared__ float xs[4][3][34];      // [ic][row][col(-1..32)]
    __shared__ float sc[CC], sh[CC];

    const int h = blockIdx.x, b = blockIdx.y;
    const int tid = threadIdx.x;
    const int tw  = tid & 7;            // 8 w-groups
    const int toc = tid >> 3;           // 32 oc-groups
    const int w0  = tw * 4;
    const int oc0 = toc * 8;

    // BN affine per channel
    {
        float s = gg[tid] * rsqrtf(gv[tid] + BN_EPS);
        sc[tid] = s;
        sh[tid] = gb[tid] - gm[tid] * s;
    }

    const float* xin = RESID ? g_out1 : x_orig;
    const float* kb  = g_kbuf + (size_t)b * KELEM;

    float acc[8][4];
    #pragma unroll
    for (int i = 0; i < 8; i++)
        #pragma unroll
        for (int j = 0; j < 4; j++) acc[i][j] = 0.f;

    for (int ic0 = 0; ic0 < CC; ic0 += 4) {
        __syncthreads();
        // stage weights: 256 oc x 36 floats (9 float4 per oc, contiguous in gmem)
        for (int idx = tid; idx < CC*9; idx += 256) {
            int oc = idx / 9, j4 = idx % 9;
            float4 v = *(const float4*)(kb + (size_t)oc*(CC*9) + ic0*9 + j4*4);
            wts[oc][j4*4+0] = v.x; wts[oc][j4*4+1] = v.y;
            wts[oc][j4*4+2] = v.z; wts[oc][j4*4+3] = v.w;
        }
        // stage x halo tile: 4 ic x 3 rows x 34 cols
        for (int idx = tid; idx < 4*3*34; idx += 256) {
            int ic = idx / 102, r = idx % 102;
            int dy = r / 34, col = r % 34;
            int hh = h + dy - 1, ww = col - 1;
            float val = 0.f;
            if ((unsigned)hh < HW && (unsigned)ww < HW)
                val = xin[(((size_t)b*CC + ic0 + ic)*HW + hh)*HW + ww];
            xs[ic][dy][col] = val;
        }
        __syncthreads();

        #pragma unroll
        for (int ic = 0; ic < 4; ic++) {
            float xv[3][6];
            #pragma unroll
            for (int dy = 0; dy < 3; dy++)
                #pragma unroll
                for (int c = 0; c < 6; c++) xv[dy][c] = xs[ic][dy][w0 + c];

            #pragma unroll
            for (int dy = 0; dy < 3; dy++)
                #pragma unroll
                for (int dx = 0; dx < 3; dx++) {
                    float wv[8];
                    #pragma unroll
                    for (int i = 0; i < 8; i++) wv[i] = wts[oc0 + i][ic*9 + dy*3 + dx];
                    #pragma unroll
                    for (int i = 0; i < 8; i++)
                        #pragma unroll
                        for (int j = 0; j < 4; j++)
                            acc[i][j] = fmaf(wv[i], xv[dy][dx + j], acc[i][j]);
                }
        }
    }

    // epilogue: BN + [residual] + ReLU, float4 stores
    float* dst = RESID ? out_param : g_out1;
    #pragma unroll
    for (int i = 0; i < 8; i++) {
        int oc = oc0 + i;
        float s = sc[oc], t = sh[oc];
        size_t base = (((size_t)b*CC + oc)*HW + h)*HW + w0;
        float4 v;
        v.x = fmaf(acc[i][0], s, t);
        v.y = fmaf(acc[i][1], s, t);
        v.z = fmaf(acc[i][2], s, t);
        v.w = fmaf(acc[i][3], s, t);
        if (RESID) {
            float4 rv = *(const float4*)(x_orig + base);
            v.x += rv.x; v.y += rv.y; v.z += rv.z; v.w += rv.w;
        }
        v.x = fmaxf(v.x, 0.f); v.y = fmaxf(v.y, 0.f);
        v.z = fmaxf(v.z, 0.f); v.w = fmaxf(v.w, 0.f);
        *(float4*)(dst + base) = v;
    }
}

// ============================================================================
extern "C" void kernel_launch(void* const* d_in, const int* in_sizes, int n_in,
                              void* d_out, int out_size) {
    const float* x  = (const float*)d_in[0];
    const float* rw = (const float*)d_in[1];
    const float* rb = (const float*)d_in[2];
    const float* w1 = (const float*)d_in[3];
    const float* w2 = (const float*)d_in[4];
    const float* g1 = (const float*)d_in[5];
    const float* b1 = (const float*)d_in[6];
    const float* m1 = (const float*)d_in[7];
    const float* v1 = (const float*)d_in[8];
    const float* g2 = (const float*)d_in[9];
    const float* b2 = (const float*)d_in[10];
    const float* m2 = (const float*)d_in[11];
    const float* v2 = (const float*)d_in[12];
    float* out = (float*)d_out;

    dim3 cgrid(HW, BB);

    router_kernel<<<BB, CC>>>(x, rw, rb);
    combine_kernel<<<KELEM/4/256, 256>>>(w1);
    conv_kernel<false><<<cgrid, 256>>>(x, g1, b1, m1, v1, nullptr);
    combine_kernel<<<KELEM/4/256, 256>>>(w2);
    conv_kernel<true><<<cgrid, 256>>>(x, g2, b2, m2, v2, out);
}

// round 3
// speedup vs baseline: 3.7582x; 3.7582x over previous
#include <cuda_runtime.h>
#include <cuda_fp16.h>
#include <cstdint>

#define BB 32
#define CC 256
#define HW 32
#define EE 8
#define KTOT 2304                 // 9 taps * 256 ic
#define KELEM (CC*CC*9)           // per-expert weight elements
#define BN_EPS 1e-5f

// ---------------- scratch (device globals, no allocations) ----------------
__device__ float  g_r[BB*EE];
__device__ __half g_kw[(size_t)BB*CC*KTOT];      // fp16 weights [b][oc][tap][ic]
__device__ __half g_xh[(size_t)BB*CC*HW*HW];     // fp16 input activations
__device__ __half g_o1[(size_t)BB*CC*HW*HW];     // fp16 intermediate activations

// ---------------- helpers ----------------
__device__ __forceinline__ uint32_t smem_u32(const void* p) {
    uint32_t a;
    asm("{ .reg .u64 t; cvta.to.shared.u64 t, %1; cvt.u32.u64 %0, t; }" : "=r"(a) : "l"(p));
    return a;
}
__device__ __forceinline__ uint32_t pack2h(__half a, __half b) {
    return (uint32_t)__half_as_ushort(a) | ((uint32_t)__half_as_ushort(b) << 16);
}

#define CP_ASYNC16(dst, src) \
    asm volatile("cp.async.cg.shared.global [%0], [%1], 16;" :: "r"(dst), "l"(src))
#define CP_COMMIT()  asm volatile("cp.async.commit_group;")
#define CP_WAIT_1()  asm volatile("cp.async.wait_group 1;")
#define CP_WAIT_0()  asm volatile("cp.async.wait_group 0;")

#define LDSM_X4(r0,r1,r2,r3,addr) \
    asm volatile("ldmatrix.sync.aligned.m8n8.x4.shared.b16 {%0,%1,%2,%3}, [%4];" \
        : "=r"(r0),"=r"(r1),"=r"(r2),"=r"(r3) : "r"(addr))
#define LDSM_X2_T(r0,r1,addr) \
    asm volatile("ldmatrix.sync.aligned.m8n8.x2.trans.shared.b16 {%0,%1}, [%2];" \
        : "=r"(r0),"=r"(r1) : "r"(addr))
#define MMA16816(d,a0,a1,a2,a3,b0,b1) \
    asm volatile("mma.sync.aligned.m16n8k16.row.col.f32.f16.f16.f32 " \
        "{%0,%1,%2,%3},{%4,%5,%6,%7},{%8,%9},{%0,%1,%2,%3};" \
        : "+f"((d)[0]),"+f"((d)[1]),"+f"((d)[2]),"+f"((d)[3]) \
        : "r"(a0),"r"(a1),"r"(a2),"r"(a3),"r"(b0),"r"(b1))

// ============================================================================
// Router: GAP -> Linear(C,E) -> sigmoid   (grid=B, block=C)
// ============================================================================
__global__ void router_kernel(const float* __restrict__ x,
                              const float* __restrict__ rw,
                              const float* __restrict__ rb) {
    __shared__ float means[CC];
    int b = blockIdx.x, c = threadIdx.x;
    const float4* xp = (const float4*)(x + ((size_t)b*CC + c)*(HW*HW));
    float s = 0.f;
    #pragma unroll 8
    for (int i = 0; i < HW*HW/4; i++) { float4 v = xp[i]; s += v.x + v.y + v.z + v.w; }
    means[c] = s * (1.0f/(HW*HW));
    __syncthreads();
    if (c < EE) {
        float d = rb[c];
        #pragma unroll 8
        for (int k = 0; k < CC; k++) d = fmaf(means[k], rw[c*CC + k], d);
        g_r[b*EE + c] = 1.0f / (1.0f + expf(-d));
    }
}

// ============================================================================
// x (fp32) -> g_xh (fp16).  grid = 8192, block = 256 (4 els/thread)
// ============================================================================
__global__ void x2h_kernel(const float* __restrict__ x) {
    size_t i = ((size_t)blockIdx.x * 256 + threadIdx.x) * 4;
    float4 v = *(const float4*)(x + i);
    uint2 u;
    u.x = pack2h(__float2half_rn(v.x), __float2half_rn(v.y));
    u.y = pack2h(__float2half_rn(v.z), __float2half_rn(v.w));
    *(uint2*)(g_xh + i) = u;
}

// ============================================================================
// Combine -> fp16, reordered:  g_kw[b][oc][tap][ic] = sum_e r[b,e]*w[e][oc][ic][tap]
// grid = 576, block = 256
// ============================================================================
__global__ void combine_kernel(const float* __restrict__ wbank) {
    __shared__ float rs[BB*EE];
    int tid = threadIdx.x;
    rs[tid] = g_r[tid];
    __syncthreads();

    int q   = blockIdx.x * 256 + tid;
    int ic0 = (q & 63) * 4;
    int tap = (q >> 6) % 9;
    int oc  = q / 576;

    float v[EE][4];
    const float* base = wbank + (size_t)oc*KTOT + (size_t)ic0*9 + tap;
    #pragma unroll
    for (int e = 0; e < EE; e++) {
        const float* p = base + (size_t)e * KELEM;
        #pragma unroll
        for (int j = 0; j < 4; j++) v[e][j] = p[j*9];
    }
    size_t dbase = ((size_t)oc*9 + tap)*256 + ic0;
    #pragma unroll
    for (int b = 0; b < BB; b++) {
        float a0=0.f, a1=0.f, a2=0.f, a3=0.f;
        #pragma unroll
        for (int e = 0; e < EE; e++) {
            float r = rs[b*EE + e];
            a0 = fmaf(r, v[e][0], a0); a1 = fmaf(r, v[e][1], a1);
            a2 = fmaf(r, v[e][2], a2); a3 = fmaf(r, v[e][3], a3);
        }
        uint2 u;
        u.x = pack2h(__float2half_rn(a0), __float2half_rn(a1));
        u.y = pack2h(__float2half_rn(a2), __float2half_rn(a3));
        *(uint2*)(g_kw + (size_t)b*(CC*KTOT) + dbase) = u;
    }
}

// ============================================================================
// HMMA implicit-GEMM conv3x3 + BN + [residual] + ReLU
// grid = (16 ntile, 32 b, 2 mblk), block = 256 (8 warps, 4Mx2N warp grid)
// D[128 oc][64 pos] = sum_k W[oc][k]*X[k][pos], K = 36 stages of 64
// smem: A 2x16KB (swizzled [128 oc][64 k]) + B 2x8KB ([64 k][64 n]) = 48KB
// ============================================================================
struct __align__(1024) ConvSmem {
    __half A[2][128*64];
    __half B[2][64*64];
};

template<bool RESID>
__global__ void __launch_bounds__(256, 2)
conv_mma_kernel(const float* __restrict__ x_orig,
                const float* __restrict__ gg, const float* __restrict__ gb,
                const float* __restrict__ gm, const float* __restrict__ gv,
                float* __restrict__ out_param) {
    __shared__ ConvSmem sm;

    const int ntile = blockIdx.x;          // 0..15  (64 positions = 2 h rows)
    const int b     = blockIdx.y;
    const int mblk  = blockIdx.z;          // 0/1 -> oc 0..127 / 128..255
    const int tid   = threadIdx.x;
    const int wid   = tid >> 5;
    const int lid   = tid & 31;
    const int wm    = wid & 3;             // M warp (32 rows)
    const int wn    = wid >> 2;            // N warp (32 cols)
    const int m0    = wm * 32;
    const int n0    = wn * 32;
    const int h0    = ntile * 2;
    const int pos0  = ntile * 64;

    const __half* kwb = g_kw + (size_t)b*(CC*KTOT) + (size_t)mblk*128*KTOT;
    const __half* xin = (RESID ? g_o1 : g_xh) + (size_t)b*(CC*HW*HW);

    const uint32_t sA = smem_u32(sm.A[0]);
    const uint32_t sB = smem_u32(sm.B[0]);

    // ---- A copy mapping: 1024 chunks of 16B (128 rows x 8 chunks), 4/thread
    const int arow = tid >> 3;             // base row step 32 per iter
    const int achk = tid & 7;

    // ---- B build mapping: row br (k/ic), 16 cols starting bn0
    const int br  = tid >> 2;
    const int bn0 = (tid & 3) * 16;
    const int hsub = bn0 >> 5;

    auto buildA = [&](int s, int bi) {
        const int tap = s >> 2, ic0 = (s & 3) * 64;
        const __half* src0 = kwb + (size_t)tap*256 + ic0;
        uint32_t dst0 = sA + bi*16384;
        #pragma unroll
        for (int i = 0; i < 4; i++) {
            int row = arow + i*32;
            const __half* src = src0 + (size_t)row*KTOT + achk*8;
            uint32_t dst = dst0 + row*128 + (((achk ^ (row & 7))) << 4);
            CP_ASYNC16(dst, src);
        }
    };
    auto buildB = [&](int s, int bi) {
        const int tap = s >> 2, ic0 = (s & 3) * 64;
        const int dy = tap / 3, dx = tap % 3;
        int hsrc = h0 + hsub + dy - 1;
        bool hok = (unsigned)hsrc < HW;
        const __half* srow = xin + ((size_t)(ic0 + br)*HW + (hok ? hsrc : 0))*HW;
        __half vals[16];
        #pragma unroll
        for (int j = 0; j < 16; j++) {
            int w = (bn0 & 31) + j + dx - 1;
            vals[j] = (hok && (unsigned)w < HW) ? srow[w] : __ushort_as_half((unsigned short)0);
        }
        uint32_t dst0 = sB + bi*8192 + br*128;
        #pragma unroll
        for (int qd = 0; qd < 4; qd++) {
            uint2 u;
            u.x = pack2h(vals[qd*4+0], vals[qd*4+1]);
            u.y = pack2h(vals[qd*4+2], vals[qd*4+3]);
            int c = 2*(tid & 3) + (qd >> 1);
            uint32_t dst = dst0 + ((c ^ (br & 7)) << 4) + (qd & 1)*8;
            *(uint2*)(uintptr_t)( (char*)sm.B[0] - (char*)sm.B[0] ) ; // no-op keep types
            asm volatile("st.shared.v2.b32 [%0], {%1, %2};" :: "r"(dst), "r"(u.x), "r"(u.y) : "memory");
        }
    };

    float acc[2][4][4];
    #pragma unroll
    for (int mi = 0; mi < 2; mi++)
        #pragma unroll
        for (int ni = 0; ni < 4; ni++)
            #pragma unroll
            for (int k = 0; k < 4; k++) acc[mi][ni][k] = 0.f;

    // prologue
    buildA(0, 0); buildB(0, 0); CP_COMMIT();

    const int rA0 = m0 + (lid & 15);
    const int rA1 = m0 + 16 + (lid & 15);
    const int krl = lid & 15;

    for (int s = 0; s < 36; s++) {
        const int bi = s & 1;
        if (s < 35) {
            buildA(s + 1, bi ^ 1);
            buildB(s + 1, bi ^ 1);
            CP_COMMIT();
            CP_WAIT_1();
        } else {
            CP_WAIT_0();
        }
        __syncthreads();

        const uint32_t bufA = sA + bi*16384;
        const uint32_t bufB = sB + bi*8192;

        #pragma unroll
        for (int ks = 0; ks < 4; ks++) {
            uint32_t a0[4], a1[4], bf[4][2];
            {
                int ch = ks*2 + (lid >> 4);
                uint32_t ad0 = bufA + rA0*128 + (((ch ^ (rA0 & 7))) << 4);
                uint32_t ad1 = bufA + rA1*128 + (((ch ^ (rA1 & 7))) << 4);
                LDSM_X4(a0[0], a0[1], a0[2], a0[3], ad0);
                LDSM_X4(a1[0], a1[1], a1[2], a1[3], ad1);
            }
            {
                int kr = ks*16 + krl;
                uint32_t bd = bufB + kr*128;
                int sw = (kr & 7);
                #pragma unroll
                for (int ni = 0; ni < 4; ni++) {
                    int c = wn*4 + ni;
                    LDSM_X2_T(bf[ni][0], bf[ni][1], bd + ((c ^ sw) << 4));
                }
            }
            #pragma unroll
            for (int ni = 0; ni < 4; ni++) {
                MMA16816(acc[0][ni], a0[0], a0[1], a0[2], a0[3], bf[ni][0], bf[ni][1]);
                MMA16816(acc[1][ni], a1[0], a1[1], a1[2], a1[3], bf[ni][0], bf[ni][1]);
            }
        }
        __syncthreads();
    }

    // ---- epilogue: BN (+residual) + ReLU ----
    const int ocb = mblk*128 + m0 + (lid >> 2);
    float scv[2][2], shv[2][2];
    #pragma unroll
    for (int mi = 0; mi < 2; mi++)
        #pragma unroll
        for (int rh = 0; rh < 2; rh++) {
            int oc = ocb + mi*16 + rh*8;
            float sgl = gg[oc] * rsqrtf(gv[oc] + BN_EPS);
            scv[mi][rh] = sgl;
            shv[mi][rh] = gb[oc] - gm[oc] * sgl;
        }

    #pragma unroll
    for (int mi = 0; mi < 2; mi++) {
        #pragma unroll
        for (int rh = 0; rh < 2; rh++) {
            int oc = ocb + mi*16 + rh*8;
            size_t base = ((size_t)b*CC + oc)*(HW*HW) + pos0 + n0 + 2*(lid & 3);
            float s = scv[mi][rh], t = shv[mi][rh];
            #pragma unroll
            for (int ni = 0; ni < 4; ni++) {
                float v0 = fmaf(acc[mi][ni][rh*2 + 0], s, t);
                float v1 = fmaf(acc[mi][ni][rh*2 + 1], s, t);
                size_t idx = base + ni*8;
                if (RESID) {
                    float2 rv = *(const float2*)(x_orig + idx);
                    v0 = fmaxf(v0 + rv.x, 0.f);
                    v1 = fmaxf(v1 + rv.y, 0.f);
                    *(float2*)(out_param + idx) = make_float2(v0, v1);
                } else {
                    v0 = fmaxf(v0, 0.f);
                    v1 = fmaxf(v1, 0.f);
                    uint32_t u = pack2h(__float2half_rn(v0), __float2half_rn(v1));
                    *(uint32_t*)(g_o1 + idx) = u;
                }
            }
        }
    }
}

// ============================================================================
extern "C" void kernel_launch(void* const* d_in, const int* in_sizes, int n_in,
                              void* d_out, int out_size) {
    const float* x  = (const float*)d_in[0];
    const float* rw = (const float*)d_in[1];
    const float* rb = (const float*)d_in[2];
    const float* w1 = (const float*)d_in[3];
    const float* w2 = (const float*)d_in[4];
    const float* g1 = (const float*)d_in[5];
    const float* b1 = (const float*)d_in[6];
    const float* m1 = (const float*)d_in[7];
    const float* v1 = (const float*)d_in[8];
    const float* g2 = (const float*)d_in[9];
    const float* b2 = (const float*)d_in[10];
    const float* m2 = (const float*)d_in[11];
    const float* v2 = (const float*)d_in[12];
    float* out = (float*)d_out;

    dim3 cgrid(16, BB, 2);

    router_kernel<<<BB, CC>>>(x, rw, rb);
    x2h_kernel<<<(BB*CC*HW*HW)/(256*4), 256>>>(x);
    combine_kernel<<<576, 256>>>(w1);
    conv_mma_kernel<false><<<cgrid, 256>>>(x, g1, b1, m1, v1, nullptr);
    combine_kernel<<<576, 256>>>(w2);
    conv_mma_kernel<true><<<cgrid, 256>>>(x, g2, b2, m2, v2, out);
}

// round 4
// speedup vs baseline: 6.4662x; 1.7206x over previous
#include <cuda_runtime.h>
#include <cuda_fp16.h>
#include <cstdint>

#define BB 32
#define CC 256
#define HW 32
#define EE 8
#define KTOT 2304                 // 9 taps * 256 ic
#define KELEM (CC*CC*9)           // per-expert weight elements
#define BN_EPS 1e-5f

// ---------------- scratch (device globals, no allocations) ----------------
__device__ float  g_r[BB*EE];
__device__ __half g_kw[(size_t)BB*CC*KTOT];      // fp16 weights [b][oc][tap][ic]
__device__ __half g_xh[(size_t)BB*HW*HW*CC];     // fp16 NHWC input  [b][pos][ic]
__device__ __half g_o1[(size_t)BB*HW*HW*CC];     // fp16 NHWC intermediate

// ---------------- helpers ----------------
__device__ __forceinline__ uint32_t smem_u32(const void* p) {
    uint32_t a;
    asm("{ .reg .u64 t; cvta.to.shared.u64 t, %1; cvt.u32.u64 %0, t; }" : "=r"(a) : "l"(p));
    return a;
}
__device__ __forceinline__ uint32_t pack2h(__half a, __half b) {
    return (uint32_t)__half_as_ushort(a) | ((uint32_t)__half_as_ushort(b) << 16);
}

#define CP_ASYNC16(dst, src) \
    asm volatile("cp.async.cg.shared.global [%0], [%1], 16;" :: "r"(dst), "l"(src))
#define CP_ASYNC16Z(dst, src, sz) \
    asm volatile("cp.async.cg.shared.global [%0], [%1], 16, %2;" :: "r"(dst), "l"(src), "r"(sz))
#define CP_COMMIT()  asm volatile("cp.async.commit_group;")
#define CP_WAIT_1()  asm volatile("cp.async.wait_group 1;")

#define LDSM_X4(r0,r1,r2,r3,addr) \
    asm volatile("ldmatrix.sync.aligned.m8n8.x4.shared.b16 {%0,%1,%2,%3}, [%4];" \
        : "=r"(r0),"=r"(r1),"=r"(r2),"=r"(r3) : "r"(addr))
#define MMA16816(d,a0,a1,a2,a3,b0,b1) \
    asm volatile("mma.sync.aligned.m16n8k16.row.col.f32.f16.f16.f32 " \
        "{%0,%1,%2,%3},{%4,%5,%6,%7},{%8,%9},{%0,%1,%2,%3};" \
        : "+f"((d)[0]),"+f"((d)[1]),"+f"((d)[2]),"+f"((d)[3]) \
        : "r"(a0),"r"(a1),"r"(a2),"r"(a3),"r"(b0),"r"(b1))

// ============================================================================
// Router: GAP -> Linear(C,E) -> sigmoid   (grid=B, block=C)  (x is NCHW fp32)
// ============================================================================
__global__ void router_kernel(const float* __restrict__ x,
                              const float* __restrict__ rw,
                              const float* __restrict__ rb) {
    __shared__ float means[CC];
    int b = blockIdx.x, c = threadIdx.x;
    const float4* xp = (const float4*)(x + ((size_t)b*CC + c)*(HW*HW));
    float s = 0.f;
    #pragma unroll 8
    for (int i = 0; i < HW*HW/4; i++) { float4 v = xp[i]; s += v.x + v.y + v.z + v.w; }
    means[c] = s * (1.0f/(HW*HW));
    __syncthreads();
    if (c < EE) {
        float d = rb[c];
        #pragma unroll 8
        for (int k = 0; k < CC; k++) d = fmaf(means[k], rw[c*CC + k], d);
        g_r[b*EE + c] = 1.0f / (1.0f + expf(-d));
    }
}

// ============================================================================
// NCHW fp32 -> NHWC fp16 transpose-convert. grid = (32 b * 32 h), block 256.
// thread: w = tid&31 fixed, ic chunk = (tid>>5)*32, 32 ics in registers.
// ============================================================================
__global__ void x2h_kernel(const float* __restrict__ x) {
    int blk = blockIdx.x;
    int b = blk >> 5, h = blk & 31;
    int tid = threadIdx.x;
    int w = tid & 31;
    int ic0 = (tid >> 5) * 32;

    __half vals[32];
    #pragma unroll
    for (int j = 0; j < 32; j++) {
        float v = x[(((size_t)b*CC + ic0 + j)*HW + h)*HW + w];
        vals[j] = __float2half_rn(v);
    }
    __half* dst = g_xh + (((size_t)b*HW*HW) + h*HW + w)*CC + ic0;
    #pragma unroll
    for (int q = 0; q < 4; q++) {
        uint4 u;
        u.x = pack2h(vals[q*8+0], vals[q*8+1]);
        u.y = pack2h(vals[q*8+2], vals[q*8+3]);
        u.z = pack2h(vals[q*8+4], vals[q*8+5]);
        u.w = pack2h(vals[q*8+6], vals[q*8+7]);
        *(uint4*)(dst + q*8) = u;
    }
}

// ============================================================================
// Combine -> fp16:  g_kw[b][oc][tap][ic] = sum_e r[b,e]*w[e][oc][ic][tap]
// grid = 576, block = 256
// ============================================================================
__global__ void combine_kernel(const float* __restrict__ wbank) {
    __shared__ float rs[BB*EE];
    int tid = threadIdx.x;
    rs[tid] = g_r[tid];
    __syncthreads();

    int q   = blockIdx.x * 256 + tid;
    int ic0 = (q & 63) * 4;
    int tap = (q >> 6) % 9;
    int oc  = q / 576;

    float v[EE][4];
    const float* base = wbank + (size_t)oc*KTOT + (size_t)ic0*9 + tap;
    #pragma unroll
    for (int e = 0; e < EE; e++) {
        const float* p = base + (size_t)e * KELEM;
        #pragma unroll
        for (int j = 0; j < 4; j++) v[e][j] = p[j*9];
    }
    size_t dbase = ((size_t)oc*9 + tap)*256 + ic0;
    #pragma unroll
    for (int b = 0; b < BB; b++) {
        float a0=0.f, a1=0.f, a2=0.f, a3=0.f;
        #pragma unroll
        for (int e = 0; e < EE; e++) {
            float r = rs[b*EE + e];
            a0 = fmaf(r, v[e][0], a0); a1 = fmaf(r, v[e][1], a1);
            a2 = fmaf(r, v[e][2], a2); a3 = fmaf(r, v[e][3], a3);
        }
        uint2 u;
        u.x = pack2h(__float2half_rn(a0), __float2half_rn(a1));
        u.y = pack2h(__float2half_rn(a2), __float2half_rn(a3));
        *(uint2*)(g_kw + (size_t)b*(CC*KTOT) + dbase) = u;
    }
}

// ============================================================================
// NHWC implicit-GEMM conv3x3 + BN + [residual] + ReLU
// grid = (8 ptile, 32 b, 2 nblk), block = 256 (8 warps: 2M x 4N)
// CTA tile: M=128 pos x N=128 oc, K = 36 stages (4 icc x 9 taps) of 64.
// smem (dynamic 82048B): slab[2][192 rows x 128B] + zerorow + wt[2][128 x 128B]
// ============================================================================
#define SMEM_BYTES 82048

template<bool RESID>
__global__ void __launch_bounds__(256, 2)
conv_mma_kernel(const float* __restrict__ x_orig,
                const float* __restrict__ gg, const float* __restrict__ gb,
                const float* __restrict__ gm, const float* __restrict__ gv,
                float* __restrict__ out_param) {
    extern __shared__ __align__(1024) char dsm[];

    const int ptile = blockIdx.x;          // 0..7  -> 128 positions (4 h rows)
    const int b     = blockIdx.y;
    const int nblk  = blockIdx.z;          // 0..1  -> oc halves
    const int tid   = threadIdx.x;
    const int lid   = tid & 31;
    const int wid   = tid >> 5;
    const int wm    = wid & 1;             // M warp (64 pos)
    const int wn    = wid >> 1;            // N warp (32 oc)
    const int h0    = ptile * 4;

    const uint32_t sbase = smem_u32(dsm);
    const uint32_t SLAB0 = sbase;
    const uint32_t SLAB1 = sbase + 24576;
    const uint32_t ZROW  = sbase + 49152;
    const uint32_t WT0   = sbase + 49280;
    const uint32_t WT1   = WT0 + 16384;

    const __half* xin = (RESID ? g_o1 : g_xh) + (size_t)b*(HW*HW*CC);   // NHWC
    const __half* kwb = g_kw + (size_t)b*(CC*KTOT) + (size_t)(nblk*128)*KTOT;

    if (tid < 32) *(uint32_t*)(dsm + 49152 + tid*4) = 0u;   // zero row

    // ---- slab fill: 192 rows (6 h' x 32 w) x 64 ic, zero-fill OOB h ----
    auto fillSlab = [&](int icc, uint32_t buf) {
        const int ic0 = icc * 64;
        #pragma unroll
        for (int it = 0; it < 6; it++) {
            int idx = it*256 + tid;
            int row = idx >> 3, ck = idx & 7;
            int rr = row >> 5, w = row & 31;
            int hh = h0 - 1 + rr;
            uint32_t ok = ((unsigned)hh < HW) ? 16u : 0u;
            int hcl = hh < 0 ? 0 : (hh > 31 ? 31 : hh);
            const __half* src = xin + ((size_t)(hcl*HW + w)*CC + ic0 + ck*8);
            uint32_t dst = buf + row*128 + (((uint32_t)(ck ^ (row & 7))) << 4);
            CP_ASYNC16Z(dst, src, ok);
        }
    };
    // ---- weight fill: 128 oc rows x 64 ic ----
    auto fillW = [&](int s, uint32_t buf) {
        const int icc = s / 9, tap = s - icc*9;
        const int ic0 = icc * 64;
        #pragma unroll
        for (int it = 0; it < 4; it++) {
            int idx = it*256 + tid;
            int row = idx >> 3, ck = idx & 7;
            const __half* src = kwb + (size_t)row*KTOT + tap*256 + ic0 + ck*8;
            uint32_t dst = buf + row*128 + (((uint32_t)(ck ^ (row & 7))) << 4);
            CP_ASYNC16(dst, src);
        }
    };

    float acc[4][4][4];
    #pragma unroll
    for (int mt = 0; mt < 4; mt++)
        #pragma unroll
        for (int nb = 0; nb < 4; nb++)
            #pragma unroll
            for (int k = 0; k < 4; k++) acc[mt][nb][k] = 0.f;

    fillSlab(0, SLAB0);
    fillW(0, WT0);
    CP_COMMIT();

    const int lrow = lid & 15;
    const int hi16 = lid >> 4;

    for (int s = 0; s < 36; s++) {
        const int icc = s / 9;
        const int tap = s - icc*9;
        const int dy = tap / 3, dx = tap - dy*3;

        if (s < 35) fillW(s + 1, ((s + 1) & 1) ? WT1 : WT0);
        if (tap == 0 && icc < 3) fillSlab(icc + 1, ((icc + 1) & 1) ? SLAB1 : SLAB0);
        CP_COMMIT();
        CP_WAIT_1();
        __syncthreads();

        const uint32_t slab = (icc & 1) ? SLAB1 : SLAB0;
        const uint32_t wbuf = (s & 1) ? WT1 : WT0;

        // per-lane A row pointers (tap shift folded into row index; OOB -> zero row)
        uint32_t aRow[4]; uint32_t aSw[4];
        #pragma unroll
        for (int mt = 0; mt < 4; mt++) {
            int p  = wm*64 + mt*16 + lrow;
            int hl = p >> 5, w = p & 31;
            int wp = w + dx - 1;
            int srow = (hl + dy)*32 + wp;
            bool v = (unsigned)wp < (unsigned)HW;
            aRow[mt] = v ? (slab + srow*128) : ZROW;
            aSw[mt]  = v ? (uint32_t)(srow & 7) : 0u;
        }
        uint32_t bRow[2]; uint32_t bSw[2];
        #pragma unroll
        for (int nt = 0; nt < 2; nt++) {
            int oc = wn*32 + nt*16 + lrow;
            bRow[nt] = wbuf + oc*128;
            bSw[nt]  = (uint32_t)(oc & 7);
        }

        #pragma unroll
        for (int k = 0; k < 4; k++) {
            const uint32_t ck = (uint32_t)(k*2 + hi16);
            uint32_t a[4][4], bm[2][4];
            #pragma unroll
            for (int mt = 0; mt < 4; mt++)
                LDSM_X4(a[mt][0], a[mt][1], a[mt][2], a[mt][3],
                        aRow[mt] + ((ck ^ aSw[mt]) << 4));
            #pragma unroll
            for (int nt = 0; nt < 2; nt++)
                LDSM_X4(bm[nt][0], bm[nt][1], bm[nt][2], bm[nt][3],
                        bRow[nt] + ((ck ^ bSw[nt]) << 4));
            #pragma unroll
            for (int mt = 0; mt < 4; mt++) {
                #pragma unroll
                for (int nt = 0; nt < 2; nt++) {
                    MMA16816(acc[mt][nt*2+0], a[mt][0],a[mt][1],a[mt][2],a[mt][3],
                             bm[nt][0], bm[nt][2]);
                    MMA16816(acc[mt][nt*2+1], a[mt][0],a[mt][1],a[mt][2],a[mt][3],
                             bm[nt][1], bm[nt][3]);
                }
            }
        }
        __syncthreads();
    }

    // ---- epilogue: BN (+residual) + ReLU ----
    const int posBase = ptile*128 + wm*64;
    #pragma unroll
    for (int nb = 0; nb < 4; nb++) {
        int oc = nblk*128 + wn*32 + nb*8 + (lid & 3)*2;
        float s0 = gg[oc]   * rsqrtf(gv[oc]   + BN_EPS);
        float t0 = gb[oc]   - gm[oc]   * s0;
        float s1 = gg[oc+1] * rsqrtf(gv[oc+1] + BN_EPS);
        float t1 = gb[oc+1] - gm[oc+1] * s1;
        #pragma unroll
        for (int mt = 0; mt < 4; mt++) {
            #pragma unroll
            for (int rh = 0; rh < 2; rh++) {
                int pos = posBase + mt*16 + (lid >> 2) + rh*8;
                float v0 = fmaf(acc[mt][nb][rh*2+0], s0, t0);
                float v1 = fmaf(acc[mt][nb][rh*2+1], s1, t1);
                if (RESID) {
                    size_t i0 = ((size_t)b*CC + oc)*(HW*HW) + pos;
                    size_t i1 = i0 + (HW*HW);
                    v0 = fmaxf(v0 + x_orig[i0], 0.f);
                    v1 = fmaxf(v1 + x_orig[i1], 0.f);
                    out_param[i0] = v0;
                    out_param[i1] = v1;
                } else {
                    v0 = fmaxf(v0, 0.f);
                    v1 = fmaxf(v1, 0.f);
                    size_t idx = ((size_t)b*(HW*HW) + pos)*CC + oc;
                    *(uint32_t*)(g_o1 + idx) = pack2h(__float2half_rn(v0),
                                                      __float2half_rn(v1));
                }
            }
        }
    }
}

// ============================================================================
extern "C" void kernel_launch(void* const* d_in, const int* in_sizes, int n_in,
                              void* d_out, int out_size) {
    const float* x  = (const float*)d_in[0];
    const float* rw = (const float*)d_in[1];
    const float* rb = (const float*)d_in[2];
    const float* w1 = (const float*)d_in[3];
    const float* w2 = (const float*)d_in[4];
    const float* g1 = (const float*)d_in[5];
    const float* b1 = (const float*)d_in[6];
    const float* m1 = (const float*)d_in[7];
    const float* v1 = (const float*)d_in[8];
    const float* g2 = (const float*)d_in[9];
    const float* b2 = (const float*)d_in[10];
    const float* m2 = (const float*)d_in[11];
    const float* v2 = (const float*)d_in[12];
    float* out = (float*)d_out;

    static bool attr_done = false;
    if (!attr_done) {
        cudaFuncSetAttribute(conv_mma_kernel<false>,
                             cudaFuncAttributeMaxDynamicSharedMemorySize, SMEM_BYTES);
        cudaFuncSetAttribute(conv_mma_kernel<true>,
                             cudaFuncAttributeMaxDynamicSharedMemorySize, SMEM_BYTES);
        attr_done = true;
    }

    dim3 cgrid(8, BB, 2);

    router_kernel<<<BB, CC>>>(x, rw, rb);
    x2h_kernel<<<BB*HW, 256>>>(x);
    combine_kernel<<<576, 256>>>(w1);
    conv_mma_kernel<false><<<cgrid, 256, SMEM_BYTES>>>(x, g1, b1, m1, v1, nullptr);
    combine_kernel<<<576, 256>>>(w2);
    conv_mma_kernel<true><<<cgrid, 256, SMEM_BYTES>>>(x, g2, b2, m2, v2, out);
}